// round 13
// baseline (speedup 1.0000x reference)
#include <cuda_runtime.h>
#include <cuda_fp16.h>
#include <cstdint>

// Problem constants
#define B_   64
#define S_   512
#define D_   768
#define H_   12
#define DH_  64
#define P_   256
#define N3_  2304
#define KE_  1536   // stored extended K (hi 768 | lo 768), fp16

#define ATTN_SZ   (B_*P_*D_)
#define NM_OFF    (ATTN_SZ)
#define RQ_OFF    (ATTN_SZ + B_*P_)

// Scratch. K/V + A compacted PER-BATCH: slot < cnt[b]; slots >= cnt stay zero.
__device__ __half g_k[B_*H_*S_*DH_];
__device__ __half g_v[B_*H_*S_*DH_];
__device__ __half g_aextc[B_*S_*KE_];    // [b*512+slot] unmasked rows, hi|lo
__device__ __half g_apool[B_*P_*KE_];    // pooled rows, hi|lo
__device__ __half g_bext[N3_*KE_];       // [2304][1536]  W^T hi|lo
// compaction bookkeeping
__device__ int g_cnt[B_];
__device__ int g_lp[B_*S_];
__device__ int g_gidx[B_*S_];            // [b*512+slot] = orig s (within batch)

// ---------------- PTX helpers ----------------
__device__ __forceinline__ uint32_t smem_u32(const void* p) {
    uint32_t a;
    asm("{ .reg .u64 t; cvta.to.shared.u64 t, %1; cvt.u32.u64 %0, t; }" : "=r"(a) : "l"(p));
    return a;
}
#define SWZ128(o) ((o) ^ (((o) >> 3) & 0x70))

__device__ __forceinline__ void cp_async16(uint32_t dst, const void* src) {
    asm volatile("cp.async.cg.shared.global [%0], [%1], 16;" :: "r"(dst), "l"(src) : "memory");
}
__device__ __forceinline__ void cp_commit() {
    asm volatile("cp.async.commit_group;" ::: "memory");
}
template<int N>
__device__ __forceinline__ void cp_wait() {
    asm volatile("cp.async.wait_group %0;" :: "n"(N) : "memory");
}
__device__ __forceinline__ void ldsm4(uint32_t* r, uint32_t addr) {
    asm volatile("ldmatrix.sync.aligned.m8n8.x4.shared.b16 {%0,%1,%2,%3}, [%4];"
        : "=r"(r[0]), "=r"(r[1]), "=r"(r[2]), "=r"(r[3]) : "r"(addr));
}
__device__ __forceinline__ void ldsm4t(uint32_t* r, uint32_t addr) {
    asm volatile("ldmatrix.sync.aligned.m8n8.x4.trans.shared.b16 {%0,%1,%2,%3}, [%4];"
        : "=r"(r[0]), "=r"(r[1]), "=r"(r[2]), "=r"(r[3]) : "r"(addr));
}
__device__ __forceinline__ void mma16816(float* c, const uint32_t* a, uint32_t b0, uint32_t b1) {
    asm volatile("mma.sync.aligned.m16n8k16.row.col.f32.f16.f16.f32 "
        "{%0,%1,%2,%3}, {%4,%5,%6,%7}, {%8,%9}, {%0,%1,%2,%3};"
        : "+f"(c[0]), "+f"(c[1]), "+f"(c[2]), "+f"(c[3])
        : "r"(a[0]), "r"(a[1]), "r"(a[2]), "r"(a[3]), "r"(b0), "r"(b1));
}
__device__ __forceinline__ uint32_t cvt_f16x2(float hi, float lo) {
    uint32_t r;
    asm("cvt.rn.f16x2.f32 %0, %1, %2;" : "=r"(r) : "f"(hi), "f"(lo));
    return r;
}
__device__ __forceinline__ float2 unpack_h2(uint32_t u) {
    __half2 h = *reinterpret_cast<__half2*>(&u);
    return make_float2(__low2float(h), __high2float(h));
}
__device__ __forceinline__ void split4(float4 a, uint2& ph, uint2& pl) {
    __half h0 = __float2half_rn(a.x), h1 = __float2half_rn(a.y);
    __half h2 = __float2half_rn(a.z), h3 = __float2half_rn(a.w);
    __half l0 = __float2half_rn(a.x - __half2float(h0));
    __half l1 = __float2half_rn(a.y - __half2float(h1));
    __half l2 = __float2half_rn(a.z - __half2float(h2));
    __half l3 = __float2half_rn(a.w - __half2float(h3));
    ph.x = (uint32_t)__half_as_ushort(h0) | ((uint32_t)__half_as_ushort(h1) << 16);
    ph.y = (uint32_t)__half_as_ushort(h2) | ((uint32_t)__half_as_ushort(h3) << 16);
    pl.x = (uint32_t)__half_as_ushort(l0) | ((uint32_t)__half_as_ushort(l1) << 16);
    pl.y = (uint32_t)__half_as_ushort(l2) | ((uint32_t)__half_as_ushort(l3) << 16);
}

// ---------------- scan: per-batch prefix + gidx + new_mask, one launch ----------------
__global__ __launch_bounds__(512)
void scan_a(const int* __restrict__ mask, float* __restrict__ out_nm)
{
    __shared__ int wsum[16];
    __shared__ int woff[16];
    int b = blockIdx.x, s = threadIdx.x;
    int v = mask[b * S_ + s] != 0;
    unsigned bal = __ballot_sync(0xffffffffu, v);
    int lane = s & 31, w = s >> 5;
    int wpre = __popc(bal & ((1u << lane) - 1u));
    if (lane == 31) wsum[w] = __popc(bal);
    if (s < 256)
        out_nm[b * P_ + s] = (float)(mask[b * S_ + 2 * s] | mask[b * S_ + 2 * s + 1]);
    __syncthreads();
    if (s == 0) {
        int acc = 0;
        #pragma unroll
        for (int i = 0; i < 16; i++) { woff[i] = acc; acc += wsum[i]; }
        g_cnt[b] = acc;
    }
    __syncthreads();
    if (v) {
        int slot = woff[w] + wpre;
        g_lp[b * S_ + s] = slot;
        g_gidx[b * S_ + slot] = s;
    }
}

// ---------------- fused hidden split ----------------
__global__ __launch_bounds__(192)
void split_hidden(const float* __restrict__ A, const int* __restrict__ mask)
{
    int pr = blockIdx.x;                       // 0..16383
    int b = pr >> 8;
    int m0 = b * S_ + ((pr & 255) << 1);
    int k4 = threadIdx.x * 4;

    int mk0 = mask[m0], mk1 = mask[m0 + 1];
    float4 a0 = *(const float4*)&A[(size_t)m0 * D_ + k4];
    float4 a1 = *(const float4*)&A[(size_t)(m0 + 1) * D_ + k4];

    float f0 = (float)mk0, f1 = (float)mk1;
    float inv = 1.0f / fmaxf(f0 + f1, 1.0f);
    float4 ap = make_float4((f0 * a0.x + f1 * a1.x) * inv,
                            (f0 * a0.y + f1 * a1.y) * inv,
                            (f0 * a0.z + f1 * a1.z) * inv,
                            (f0 * a0.w + f1 * a1.w) * inv);
    uint2 ph, pl; split4(ap, ph, pl);
    *(uint2*)&g_apool[(size_t)pr * KE_ + k4]      = ph;
    *(uint2*)&g_apool[(size_t)pr * KE_ + D_ + k4] = pl;

    if (mk0) {
        size_t ci = (size_t)b * S_ + g_lp[m0];
        uint2 h, l; split4(a0, h, l);
        *(uint2*)&g_aextc[ci * KE_ + k4]      = h;
        *(uint2*)&g_aextc[ci * KE_ + D_ + k4] = l;
    }
    if (mk1) {
        size_t ci = (size_t)b * S_ + g_lp[m0 + 1];
        uint2 h, l; split4(a1, h, l);
        *(uint2*)&g_aextc[ci * KE_ + k4]      = h;
        *(uint2*)&g_aextc[ci * KE_ + D_ + k4] = l;
    }
}

// ---------------- Prepass W: transpose + split ----------------
__global__ __launch_bounds__(256)
void split_wT(const float* __restrict__ W)
{
    __shared__ float t[32][33];
    int n0 = blockIdx.x * 32, k0 = blockIdx.y * 32;
    int tx = threadIdx.x, ty = threadIdx.y;
    #pragma unroll
    for (int j = 0; j < 4; j++)
        t[ty + j * 8][tx] = W[(size_t)(k0 + ty + j * 8) * N3_ + n0 + tx];
    __syncthreads();
    #pragma unroll
    for (int j = 0; j < 4; j++) {
        int n = n0 + ty + j * 8;
        int k = k0 + tx;
        float v = t[tx][ty + j * 8];
        __half h = __float2half_rn(v);
        __half l = __float2half_rn(v - __half2float(h));
        g_bext[(size_t)n * KE_ + k]      = h;
        g_bext[(size_t)n * KE_ + D_ + k] = l;
    }
}

// ---------------- unified GEMM: 12 pair-iters, stage [Ah|Al|Bh], 64x64 warp tiles ----------------
// C = (Ah + Al) * Bh.  4 warps, 128 threads, 2-stage double buffer, 2 CTA/SM.
// bid < 768: q tiles (6 n x 128 m).  bid >= 768: kv, (batch*4 + t)*12 + n, early exit.
#define NP    12
#define TILEB 16384
#define STB   (3*TILEB)          // 48KB per stage
#define PITCH 132
#define SMEM_REQ (2*STB + 1024)

__global__ __launch_bounds__(128, 2)
void gemm_all(const float* __restrict__ Wb, const int* __restrict__ maskp,
              float* __restrict__ resid)
{
    extern __shared__ char dsm[];
    __shared__ __align__(16) float s_bias[128];

    char* smem_al = (char*)(((uintptr_t)dsm + 1023) & ~(uintptr_t)1023);
    const uint32_t sbase = smem_u32(smem_al);

    const int bid = blockIdx.x;
    const bool isq = bid < 768;
    int n0, m0, bb_ = 0, cnt = 0;
    const char* agbase;
    if (isq) {
        n0 = (bid % 6) * 128;
        m0 = (bid / 6) * 128;
        agbase = (const char*)g_apool + (size_t)m0 * (KE_ * 2);
    } else {
        int r = bid - 768;
        int bslot = r / 12;            // batch*4 + t
        bb_ = bslot >> 2;
        int t = bslot & 3;
        cnt = g_cnt[bb_];
        m0 = t * 128;
        if (m0 >= cnt) return;
        n0 = 768 + (r % 12) * 128;
        agbase = (const char*)g_aextc + ((size_t)bb_ * S_ + m0) * (KE_ * 2);
    }
    const char* bgbase = (const char*)g_bext + (size_t)n0 * (KE_ * 2);

    const int tid = threadIdx.x;
    const int wid = tid >> 5, lane = tid & 31;
    const int wm = wid & 1, wn = wid >> 1;     // warp tile 64(m) x 64(n)

    s_bias[tid] = Wb[n0 + tid];

    uint32_t ld_off[8];
    int g_offv[8];
    #pragma unroll
    for (int p = 0; p < 8; p++) {
        int idx = p * 128 + tid;
        int row = idx >> 3, seg = (idx & 7) * 16;
        ld_off[p] = SWZ128(row * 128 + seg);
        g_offv[p] = row * (KE_ * 2) + seg;
    }

    auto issue = [&](int j) {                 // pair j: Ah(j), Al(j), Bh(j)
        const char* ah = agbase + j * 128;
        const char* al = agbase + 1536 + j * 128;
        const char* bh = bgbase + j * 128;
        uint32_t base = sbase + (j & 1) * STB;
        #pragma unroll
        for (int p = 0; p < 8; p++)
            cp_async16(base + ld_off[p], ah + g_offv[p]);
        #pragma unroll
        for (int p = 0; p < 8; p++)
            cp_async16(base + TILEB + ld_off[p], al + g_offv[p]);
        #pragma unroll
        for (int p = 0; p < 8; p++)
            cp_async16(base + 2 * TILEB + ld_off[p], bh + g_offv[p]);
        cp_commit();
    };

    float c[4][8][4];
    #pragma unroll
    for (int i = 0; i < 4; i++)
        #pragma unroll
        for (int j = 0; j < 8; j++)
            #pragma unroll
            for (int q = 0; q < 4; q++) c[i][j][q] = 0.0f;

    uint32_t a_off[4][4], b_off[4][4];
    #pragma unroll
    for (int mi = 0; mi < 4; mi++)
        #pragma unroll
        for (int ks = 0; ks < 4; ks++) {
            int r = wm * 64 + mi * 16 + (lane & 15);
            int cb = ks * 32 + (lane >> 4) * 16;
            a_off[mi][ks] = SWZ128(r * 128 + cb);
        }
    #pragma unroll
    for (int ni = 0; ni < 4; ni++)
        #pragma unroll
        for (int ks = 0; ks < 4; ks++) {
            int r = wn * 64 + ni * 16 + (lane & 7) + ((lane >> 4) << 3);
            int cb = ks * 32 + ((lane >> 3) & 1) * 16;
            b_off[ni][ks] = 2 * TILEB + SWZ128(r * 128 + cb);
        }

    issue(0);

    for (int j = 0; j < NP; j++) {
        if (j + 1 < NP) { issue(j + 1); cp_wait<1>(); }
        else cp_wait<0>();
        __syncthreads();

        uint32_t buf = sbase + (j & 1) * STB;
        #pragma unroll
        for (int ks = 0; ks < 4; ks++) {
            uint32_t bb[4][4];
            #pragma unroll
            for (int ni = 0; ni < 4; ni++)
                ldsm4(bb[ni], buf + b_off[ni][ks]);
            uint32_t av[4][4];
            #pragma unroll
            for (int mi = 0; mi < 4; mi++)
                ldsm4(av[mi], buf + a_off[mi][ks]);
            #pragma unroll
            for (int ni = 0; ni < 4; ni++)
                #pragma unroll
                for (int mi = 0; mi < 4; mi++) {
                    mma16816(c[mi][2 * ni],     av[mi], bb[ni][0], bb[ni][1]);
                    mma16816(c[mi][2 * ni + 1], av[mi], bb[ni][2], bb[ni][3]);
                }
            #pragma unroll
            for (int mi = 0; mi < 4; mi++)
                ldsm4(av[mi], buf + TILEB + a_off[mi][ks]);
            #pragma unroll
            for (int ni = 0; ni < 4; ni++)
                #pragma unroll
                for (int mi = 0; mi < 4; mi++) {
                    mma16816(c[mi][2 * ni],     av[mi], bb[ni][0], bb[ni][1]);
                    mma16816(c[mi][2 * ni + 1], av[mi], bb[ni][2], bb[ni][3]);
                }
        }
        __syncthreads();
    }

    // ---- stage C to smem ----
    float* Csm = (float*)smem_al;
    #pragma unroll
    for (int mi = 0; mi < 4; mi++)
        #pragma unroll
        for (int nj = 0; nj < 8; nj++) {
            int row = wm * 64 + mi * 16 + (lane >> 2);
            int col = wn * 64 + nj * 8 + (lane & 3) * 2;
            *(float2*)&Csm[row * PITCH + col]       = make_float2(c[mi][nj][0], c[mi][nj][1]);
            *(float2*)&Csm[(row + 8) * PITCH + col] = make_float2(c[mi][nj][2], c[mi][nj][3]);
        }
    __syncthreads();

    const int row = tid;
    if (isq) {
        int p = m0 + row;
        int b = p >> 8, pl_ = p & 255;
        int mm = b * S_ + 2 * pl_;
        float cb = (maskp[mm] | maskp[mm + 1]) ? 1.0f : 0.0f;
        float* dst = resid + (size_t)p * D_ + n0;
        #pragma unroll
        for (int i = 0; i < 32; i++) {
            float4 x = *(float4*)&Csm[row * PITCH + i * 4];
            float4 bi = *(float4*)&s_bias[i * 4];
            *(float4*)(dst + i * 4) = make_float4(x.x + bi.x * cb, x.y + bi.y * cb,
                                                  x.z + bi.z * cb, x.w + bi.w * cb);
        }
    } else if (m0 + row < cnt) {
        int slot = m0 + row;
        int region = 1 + (n0 >= 2 * D_);
        int head0 = (n0 - region * D_) >> 6;
        __half* g = (region == 1) ? g_k : g_v;
        #pragma unroll
        for (int half = 0; half < 2; half++) {
            int cbase = half * 64;
            __half* dst = g + (((size_t)(bb_ * H_ + head0 + half)) * S_ + slot) * DH_;
            #pragma unroll
            for (int i = 0; i < 16; i++) {
                float4 x = *(float4*)&Csm[row * PITCH + cbase + i * 4];
                float4 bi = *(float4*)&s_bias[cbase + i * 4];
                uint2 o;
                o.x = cvt_f16x2(x.y + bi.y, x.x + bi.x);
                o.y = cvt_f16x2(x.w + bi.w, x.z + bi.z);
                *(uint2*)(dst + i * 4) = o;
            }
        }
    }
}

// ---------------- attention: FA2 mma.sync over COMPACTED K/V ----------------
__global__ __launch_bounds__(128)
void attn_mma(const int* __restrict__ maskp, const float* __restrict__ resid,
              float* __restrict__ out)
{
    __shared__ __align__(16) uint8_t sKV[3][8192];   // per stage: K 4KB | V 4KB
    __shared__ float sfo[512];                       // orig s per compacted slot

    const int tid = threadIdx.x;
    const int lane = tid & 31, w = tid >> 5;
    const int b = blockIdx.z, h = blockIdx.y;
    const int p0 = blockIdx.x * 128 + w * 32;

    const float slope = (h < 8) ? exp2f(-(float)(h + 1)) : exp2f(-0.5f - (float)(h - 8));
    const uint32_t sbase = smem_u32(sKV);

    const int cnt = g_cnt[b];
    const int nch = (cnt + 31) >> 5;

    #pragma unroll
    for (int i = 0; i < 4; i++) {
        int idx = tid * 4 + i;
        sfo[idx] = (idx < cnt) ? (float)g_gidx[b * S_ + idx] : 1.0e6f;
    }

    uint32_t qh[2][4][4], ql[2][4][4];
    {
        const float* qb = resid + (size_t)(b * P_) * D_ + h * 64;
        #pragma unroll
        for (int mi = 0; mi < 2; mi++)
            #pragma unroll
            for (int ks = 0; ks < 4; ks++) {
                int r0 = p0 + mi * 16 + (lane >> 2);
                int c0 = ks * 16 + (lane & 3) * 2;
                float2 v[4];
                v[0] = *(const float2*)(qb + (size_t)r0 * D_ + c0);
                v[1] = *(const float2*)(qb + (size_t)(r0 + 8) * D_ + c0);
                v[2] = *(const float2*)(qb + (size_t)r0 * D_ + c0 + 8);
                v[3] = *(const float2*)(qb + (size_t)(r0 + 8) * D_ + c0 + 8);
                #pragma unroll
                for (int j = 0; j < 4; j++) {
                    uint32_t hp = cvt_f16x2(v[j].y, v[j].x);
                    float2 hf = unpack_h2(hp);
                    qh[mi][ks][j] = hp;
                    ql[mi][ks][j] = cvt_f16x2(v[j].y - hf.y, v[j].x - hf.x);
                }
            }
    }

    uint32_t kbo[4], vbo[4];
    {
        int rk = (lane & 7) + ((lane >> 4) << 3);
        int rv = ((lane >> 3) & 1) * 8 + (lane & 7);
        #pragma unroll
        for (int ks = 0; ks < 4; ks++)
            kbo[ks] = SWZ128(rk * 128 + ks * 32 + ((lane >> 3) & 1) * 16);
        #pragma unroll
        for (int d16 = 0; d16 < 4; d16++)
            vbo[d16] = SWZ128(rv * 128 + d16 * 32 + ((lane >> 4) & 1) * 16);
    }

    float o[2][8][4];
    #pragma unroll
    for (int mi = 0; mi < 2; mi++)
        #pragma unroll
        for (int j = 0; j < 8; j++)
            #pragma unroll
            for (int q = 0; q < 4; q++) o[mi][j][q] = 0.0f;
    float mrun[2][2] = {{-1e30f, -1e30f}, {-1e30f, -1e30f}};
    float lsum[2][2] = {{0.0f, 0.0f}, {0.0f, 0.0f}};

    const __half* kg = g_k + (size_t)(b * H_ + h) * S_ * DH_;
    const __half* vg = g_v + (size_t)(b * H_ + h) * S_ * DH_;

    const int ldrow = tid >> 2;
    const int ldc   = (tid & 3) * 32;

    auto issueKV = [&](int cc) {
        int stage = cc - (cc / 3) * 3;
        uint32_t base = sbase + stage * 8192;
        const char* ks = (const char*)(kg + (size_t)(cc * 32 + ldrow) * 64) + ldc;
        const char* vs = (const char*)(vg + (size_t)(cc * 32 + ldrow) * 64) + ldc;
        #pragma unroll
        for (int i = 0; i < 2; i++) {
            uint32_t off = SWZ128(ldrow * 128 + ldc + i * 16);
            cp_async16(base + off, ks + i * 16);
            cp_async16(base + 4096 + off, vs + i * 16);
        }
        cp_commit();
    };

    issueKV(0);
    if (nch > 1) issueKV(1);

    for (int cc = 0; cc < nch; cc++) {
        const int s0 = cc * 32;
        if (cc + 2 < nch) { cp_wait<1>(); } else { cp_wait<0>(); }
        __syncthreads();
        int stage = cc - (cc / 3) * 3;
        const uint32_t k_base = sbase + stage * 8192;
        const uint32_t v_base = k_base + 4096;

        float sc[2][4][4];
        #pragma unroll
        for (int mi = 0; mi < 2; mi++)
            #pragma unroll
            for (int j = 0; j < 4; j++)
                #pragma unroll
                for (int q = 0; q < 4; q++) sc[mi][j][q] = 0.0f;

        #pragma unroll
        for (int n16 = 0; n16 < 2; n16++) {
            #pragma unroll
            for (int ks = 0; ks < 4; ks++) {
                uint32_t bh4[4];
                ldsm4(bh4, k_base + n16 * 2048 + kbo[ks]);
                #pragma unroll
                for (int mi = 0; mi < 2; mi++) {
                    mma16816(sc[mi][2*n16],   qh[mi][ks], bh4[0], bh4[1]);
                    mma16816(sc[mi][2*n16],   ql[mi][ks], bh4[0], bh4[1]);
                    mma16816(sc[mi][2*n16+1], qh[mi][ks], bh4[2], bh4[3]);
                    mma16816(sc[mi][2*n16+1], ql[mi][ks], bh4[2], bh4[3]);
                }
            }
        }

        #pragma unroll
        for (int mi = 0; mi < 2; mi++) {
            float r0f = (float)(p0 + mi * 16 + (lane >> 2));
            float r1f = r0f + 8.0f;
            float mx0 = -1e30f, mx1 = -1e30f;
            #pragma unroll
            for (int n8 = 0; n8 < 4; n8++) {
                int cl = s0 + n8 * 8 + (lane & 3) * 2;
                float c0f = sfo[cl], c1f = sfo[cl + 1];
                sc[mi][n8][0] = sc[mi][n8][0] * 0.125f - slope * fabsf(c0f - r0f);
                sc[mi][n8][1] = sc[mi][n8][1] * 0.125f - slope * fabsf(c1f - r0f);
                sc[mi][n8][2] = sc[mi][n8][2] * 0.125f - slope * fabsf(c0f - r1f);
                sc[mi][n8][3] = sc[mi][n8][3] * 0.125f - slope * fabsf(c1f - r1f);
                mx0 = fmaxf(mx0, fmaxf(sc[mi][n8][0], sc[mi][n8][1]));
                mx1 = fmaxf(mx1, fmaxf(sc[mi][n8][2], sc[mi][n8][3]));
            }
            mx0 = fmaxf(mx0, __shfl_xor_sync(0xffffffffu, mx0, 1));
            mx0 = fmaxf(mx0, __shfl_xor_sync(0xffffffffu, mx0, 2));
            mx1 = fmaxf(mx1, __shfl_xor_sync(0xffffffffu, mx1, 1));
            mx1 = fmaxf(mx1, __shfl_xor_sync(0xffffffffu, mx1, 2));
            float mn0 = fmaxf(mrun[mi][0], mx0);
            float mn1 = fmaxf(mrun[mi][1], mx1);
            float cr0 = __expf(mrun[mi][0] - mn0);
            float cr1 = __expf(mrun[mi][1] - mn1);
            mrun[mi][0] = mn0; mrun[mi][1] = mn1;
            float rs0 = 0.0f, rs1 = 0.0f;
            #pragma unroll
            for (int n8 = 0; n8 < 4; n8++) {
                sc[mi][n8][0] = __expf(sc[mi][n8][0] - mn0);
                sc[mi][n8][1] = __expf(sc[mi][n8][1] - mn0);
                sc[mi][n8][2] = __expf(sc[mi][n8][2] - mn1);
                sc[mi][n8][3] = __expf(sc[mi][n8][3] - mn1);
                rs0 += sc[mi][n8][0] + sc[mi][n8][1];
                rs1 += sc[mi][n8][2] + sc[mi][n8][3];
            }
            rs0 += __shfl_xor_sync(0xffffffffu, rs0, 1);
            rs0 += __shfl_xor_sync(0xffffffffu, rs0, 2);
            rs1 += __shfl_xor_sync(0xffffffffu, rs1, 1);
            rs1 += __shfl_xor_sync(0xffffffffu, rs1, 2);
            lsum[mi][0] = lsum[mi][0] * cr0 + rs0;
            lsum[mi][1] = lsum[mi][1] * cr1 + rs1;
            #pragma unroll
            for (int d8 = 0; d8 < 8; d8++) {
                o[mi][d8][0] *= cr0; o[mi][d8][1] *= cr0;
                o[mi][d8][2] *= cr1; o[mi][d8][3] *= cr1;
            }
        }

        #pragma unroll
        for (int ksP = 0; ksP < 2; ksP++) {
            uint32_t ph[2][4], pl[2][4];
            #pragma unroll
            for (int mi = 0; mi < 2; mi++) {
                float e0 = sc[mi][2*ksP][0], e1 = sc[mi][2*ksP][1];
                float e2 = sc[mi][2*ksP][2], e3 = sc[mi][2*ksP][3];
                float f0 = sc[mi][2*ksP+1][0], f1 = sc[mi][2*ksP+1][1];
                float f2 = sc[mi][2*ksP+1][2], f3 = sc[mi][2*ksP+1][3];
                ph[mi][0] = cvt_f16x2(e1, e0);
                ph[mi][1] = cvt_f16x2(e3, e2);
                ph[mi][2] = cvt_f16x2(f1, f0);
                ph[mi][3] = cvt_f16x2(f3, f2);
                float2 g0 = unpack_h2(ph[mi][0]);
                float2 g1 = unpack_h2(ph[mi][1]);
                float2 g2 = unpack_h2(ph[mi][2]);
                float2 g3 = unpack_h2(ph[mi][3]);
                pl[mi][0] = cvt_f16x2(e1 - g0.y, e0 - g0.x);
                pl[mi][1] = cvt_f16x2(e3 - g1.y, e2 - g1.x);
                pl[mi][2] = cvt_f16x2(f1 - g2.y, f0 - g2.x);
                pl[mi][3] = cvt_f16x2(f3 - g3.y, f2 - g3.x);
            }
            #pragma unroll
            for (int d16 = 0; d16 < 4; d16++) {
                uint32_t vh4[4];
                ldsm4t(vh4, v_base + ksP * 2048 + vbo[d16]);
                #pragma unroll
                for (int mi = 0; mi < 2; mi++) {
                    mma16816(o[mi][2*d16],   ph[mi], vh4[0], vh4[1]);
                    mma16816(o[mi][2*d16],   pl[mi], vh4[0], vh4[1]);
                    mma16816(o[mi][2*d16+1], ph[mi], vh4[2], vh4[3]);
                    mma16816(o[mi][2*d16+1], pl[mi], vh4[2], vh4[3]);
                }
            }
        }
        if (cc + 2 < nch) issueKV(cc + 2);
    }

    #pragma unroll
    for (int mi = 0; mi < 2; mi++) {
        int rp0 = p0 + mi * 16 + (lane >> 2);
        int rp1 = rp0 + 8;
        int nm0 = maskp[b * S_ + 2 * rp0] | maskp[b * S_ + 2 * rp0 + 1];
        int nm1 = maskp[b * S_ + 2 * rp1] | maskp[b * S_ + 2 * rp1 + 1];
        float s0v = nm0 ? (1.0f / lsum[mi][0]) : 0.0f;
        float s1v = nm1 ? (1.0f / lsum[mi][1]) : 0.0f;
        float* dst0 = out + (size_t)(b * P_ + rp0) * D_ + h * 64 + (lane & 3) * 2;
        float* dst1 = out + (size_t)(b * P_ + rp1) * D_ + h * 64 + (lane & 3) * 2;
        #pragma unroll
        for (int d8 = 0; d8 < 8; d8++) {
            *(float2*)(dst0 + d8 * 8) = make_float2(o[mi][d8][0] * s0v, o[mi][d8][1] * s0v);
            *(float2*)(dst1 + d8 * 8) = make_float2(o[mi][d8][2] * s1v, o[mi][d8][3] * s1v);
        }
    }
}

// ---------------- launch ----------------
extern "C" void kernel_launch(void* const* d_in, const int* in_sizes, int n_in,
                              void* d_out, int out_size)
{
    const float* hidden = (const float*)d_in[0];
    const int*   mask   = (const int*)d_in[1];
    const float* W      = (const float*)d_in[2];
    const float* Wb     = (const float*)d_in[3];
    float* out = (float*)d_out;

    float* resid = out + RQ_OFF;
    float* nmout = out + NM_OFF;

    (void)cudaFuncSetAttribute(gemm_all, cudaFuncAttributeMaxDynamicSharedMemorySize, SMEM_REQ);

    scan_a<<<B_, 512>>>(mask, nmout);
    split_hidden<<<B_ * P_, 192>>>(hidden, mask);
    split_wT<<<dim3(N3_/32, D_/32), dim3(32, 8)>>>(W);
    gemm_all<<<768 + B_*4*12, 128, SMEM_REQ>>>(Wb, mask, resid);
    attn_mma<<<dim3(2, H_, B_), 128>>>(mask, resid, out);
}

// round 15
// speedup vs baseline: 1.0952x; 1.0952x over previous
#include <cuda_runtime.h>
#include <cuda_fp16.h>
#include <cstdint>

// Problem constants
#define B_   64
#define S_   512
#define D_   768
#define H_   12
#define DH_  64
#define P_   256
#define N3_  2304
#define KE_  1536   // stored extended K (hi 768 | lo 768), fp16

#define ATTN_SZ   (B_*P_*D_)
#define NM_OFF    (ATTN_SZ)
#define RQ_OFF    (ATTN_SZ + B_*P_)

// Scratch. K/V compacted per (b,h): local slot < cnt[b]; rest stay zero.
__device__ __half g_k[B_*H_*S_*DH_];
__device__ __half g_v[B_*H_*S_*DH_];
__device__ __half g_aextc[B_*S_*KE_];    // globally compacted unmasked rows, hi|lo
__device__ __half g_apool[B_*P_*KE_];    // globally compacted pooled (nm=1) rows, hi|lo
__device__ __half g_bext[N3_*KE_];       // [2304][1536]  W^T hi|lo
// compaction bookkeeping
__device__ int g_cnt[B_];
__device__ int g_lp[B_*S_];
__device__ int g_boff[B_];
__device__ int g_mc[1];
__device__ int g_ntiles[1];
__device__ int g_gidx[B_*S_ + 128];
// pooled-q compaction
__device__ int g_cntq[B_];
__device__ int g_lpq[B_*P_];
__device__ int g_boffq[B_];
__device__ int g_mcq[1];
__device__ int g_ntilesq[1];
__device__ int g_gidxq[B_*P_];

// ---------------- PTX helpers ----------------
__device__ __forceinline__ uint32_t smem_u32(const void* p) {
    uint32_t a;
    asm("{ .reg .u64 t; cvta.to.shared.u64 t, %1; cvt.u32.u64 %0, t; }" : "=r"(a) : "l"(p));
    return a;
}
#define SWZ128(o) ((o) ^ (((o) >> 3) & 0x70))

__device__ __forceinline__ void cp_async16(uint32_t dst, const void* src) {
    asm volatile("cp.async.cg.shared.global [%0], [%1], 16;" :: "r"(dst), "l"(src) : "memory");
}
__device__ __forceinline__ void cp_commit() {
    asm volatile("cp.async.commit_group;" ::: "memory");
}
template<int N>
__device__ __forceinline__ void cp_wait() {
    asm volatile("cp.async.wait_group %0;" :: "n"(N) : "memory");
}
__device__ __forceinline__ void ldsm4(uint32_t* r, uint32_t addr) {
    asm volatile("ldmatrix.sync.aligned.m8n8.x4.shared.b16 {%0,%1,%2,%3}, [%4];"
        : "=r"(r[0]), "=r"(r[1]), "=r"(r[2]), "=r"(r[3]) : "r"(addr));
}
__device__ __forceinline__ void ldsm4t(uint32_t* r, uint32_t addr) {
    asm volatile("ldmatrix.sync.aligned.m8n8.x4.trans.shared.b16 {%0,%1,%2,%3}, [%4];"
        : "=r"(r[0]), "=r"(r[1]), "=r"(r[2]), "=r"(r[3]) : "r"(addr));
}
__device__ __forceinline__ void mma16816(float* c, const uint32_t* a, uint32_t b0, uint32_t b1) {
    asm volatile("mma.sync.aligned.m16n8k16.row.col.f32.f16.f16.f32 "
        "{%0,%1,%2,%3}, {%4,%5,%6,%7}, {%8,%9}, {%0,%1,%2,%3};"
        : "+f"(c[0]), "+f"(c[1]), "+f"(c[2]), "+f"(c[3])
        : "r"(a[0]), "r"(a[1]), "r"(a[2]), "r"(a[3]), "r"(b0), "r"(b1));
}
__device__ __forceinline__ uint32_t cvt_f16x2(float hi, float lo) {
    uint32_t r;
    asm("cvt.rn.f16x2.f32 %0, %1, %2;" : "=r"(r) : "f"(hi), "f"(lo));
    return r;
}
__device__ __forceinline__ float2 unpack_h2(uint32_t u) {
    __half2 h = *reinterpret_cast<__half2*>(&u);
    return make_float2(__low2float(h), __high2float(h));
}
__device__ __forceinline__ void split4(float4 a, uint2& ph, uint2& pl) {
    __half h0 = __float2half_rn(a.x), h1 = __float2half_rn(a.y);
    __half h2 = __float2half_rn(a.z), h3 = __float2half_rn(a.w);
    __half l0 = __float2half_rn(a.x - __half2float(h0));
    __half l1 = __float2half_rn(a.y - __half2float(h1));
    __half l2 = __float2half_rn(a.z - __half2float(h2));
    __half l3 = __float2half_rn(a.w - __half2float(h3));
    ph.x = (uint32_t)__half_as_ushort(h0) | ((uint32_t)__half_as_ushort(h1) << 16);
    ph.y = (uint32_t)__half_as_ushort(h2) | ((uint32_t)__half_as_ushort(h3) << 16);
    pl.x = (uint32_t)__half_as_ushort(l0) | ((uint32_t)__half_as_ushort(l1) << 16);
    pl.y = (uint32_t)__half_as_ushort(l2) | ((uint32_t)__half_as_ushort(l3) << 16);
}

// ---------------- scan: per-batch prefixes (kv + pooled) + new_mask ----------------
__global__ __launch_bounds__(512)
void scan_a(const int* __restrict__ mask, float* __restrict__ out_nm)
{
    __shared__ int wsum[16], woff[16];
    __shared__ int wsumq[8], woffq[8];
    int b = blockIdx.x, s = threadIdx.x;
    int lane = s & 31, w = s >> 5;

    int v = mask[b * S_ + s] != 0;
    unsigned bal = __ballot_sync(0xffffffffu, v);
    int wpre = __popc(bal & ((1u << lane) - 1u));
    if (lane == 31) wsum[w] = __popc(bal);

    int nm = 0, wpreq = 0;
    if (s < 256) {
        nm = (mask[b * S_ + 2 * s] | mask[b * S_ + 2 * s + 1]) != 0;
        out_nm[b * P_ + s] = (float)nm;
    }
    unsigned balq = __ballot_sync(0xffffffffu, nm);
    if (w < 8) {
        wpreq = __popc(balq & ((1u << lane) - 1u));
        if (lane == 31) wsumq[w] = __popc(balq);
    }
    __syncthreads();
    if (s == 0) {
        int acc = 0;
        #pragma unroll
        for (int i = 0; i < 16; i++) { woff[i] = acc; acc += wsum[i]; }
        g_cnt[b] = acc;
        int accq = 0;
        #pragma unroll
        for (int i = 0; i < 8; i++) { woffq[i] = accq; accq += wsumq[i]; }
        g_cntq[b] = accq;
    }
    __syncthreads();
    if (v) g_lp[b * S_ + s] = woff[w] + wpre;
    if (s < 256 && nm) g_lpq[b * P_ + s] = woffq[w] + wpreq;
}

__global__ void scan_b()
{
    int acc = 0, accq = 0;
    for (int i = 0; i < B_; i++) {
        g_boff[i] = acc;   acc += g_cnt[i];
        g_boffq[i] = accq; accq += g_cntq[i];
    }
    g_mc[0] = acc;
    g_mcq[0] = accq;
    int nt = (acc + 127) >> 7;
    g_ntiles[0] = nt;
    g_ntilesq[0] = (accq + 127) >> 7;
    int pad = nt * 128;
    for (int i = acc; i < pad; i++) g_gidx[i] = 0;
}

// scatter: g_gidx[global ci] = m   (needs g_boff => after scan_b)
__global__ __launch_bounds__(512)
void scatter_idx(const int* __restrict__ mask)
{
    int b = blockIdx.x, s = threadIdx.x, m = b * S_ + s;
    if (mask[m]) g_gidx[g_boff[b] + g_lp[m]] = m;
}

// ---------------- fused hidden split ----------------
__global__ __launch_bounds__(192)
void split_hidden(const float* __restrict__ A, const int* __restrict__ mask,
                  float* __restrict__ resid)
{
    int pr = blockIdx.x;                       // 0..16383
    int b = pr >> 8;
    int m0 = b * S_ + ((pr & 255) << 1);
    int k4 = threadIdx.x * 4;

    int mk0 = mask[m0], mk1 = mask[m0 + 1];
    float4 a0 = *(const float4*)&A[(size_t)m0 * D_ + k4];
    float4 a1 = *(const float4*)&A[(size_t)(m0 + 1) * D_ + k4];

    if (mk0 | mk1) {
        float f0 = (float)mk0, f1 = (float)mk1;
        float inv = 1.0f / fmaxf(f0 + f1, 1.0f);
        float4 ap = make_float4((f0 * a0.x + f1 * a1.x) * inv,
                                (f0 * a0.y + f1 * a1.y) * inv,
                                (f0 * a0.z + f1 * a1.z) * inv,
                                (f0 * a0.w + f1 * a1.w) * inv);
        uint2 ph, pl; split4(ap, ph, pl);
        size_t qi = (size_t)g_boffq[b] + g_lpq[pr];
        *(uint2*)&g_apool[qi * KE_ + k4]      = ph;
        *(uint2*)&g_apool[qi * KE_ + D_ + k4] = pl;
        if (threadIdx.x == 0) g_gidxq[qi] = pr;
    } else {
        // residual_query row is exactly zero; output buffer is poisoned -> write it
        *(float4*)&resid[(size_t)pr * D_ + k4] = make_float4(0.f, 0.f, 0.f, 0.f);
    }

    int boff = g_boff[b];
    if (mk0) {
        size_t ci = (size_t)boff + g_lp[m0];
        uint2 h, l; split4(a0, h, l);
        *(uint2*)&g_aextc[ci * KE_ + k4]      = h;
        *(uint2*)&g_aextc[ci * KE_ + D_ + k4] = l;
    }
    if (mk1) {
        size_t ci = (size_t)boff + g_lp[m0 + 1];
        uint2 h, l; split4(a1, h, l);
        *(uint2*)&g_aextc[ci * KE_ + k4]      = h;
        *(uint2*)&g_aextc[ci * KE_ + D_ + k4] = l;
    }
}

// ---------------- Prepass W: transpose + split ----------------
__global__ __launch_bounds__(256)
void split_wT(const float* __restrict__ W)
{
    __shared__ float t[32][33];
    int n0 = blockIdx.x * 32, k0 = blockIdx.y * 32;
    int tx = threadIdx.x, ty = threadIdx.y;
    #pragma unroll
    for (int j = 0; j < 4; j++)
        t[ty + j * 8][tx] = W[(size_t)(k0 + ty + j * 8) * N3_ + n0 + tx];
    __syncthreads();
    #pragma unroll
    for (int j = 0; j < 4; j++) {
        int n = n0 + ty + j * 8;
        int k = k0 + tx;
        float v = t[tx][ty + j * 8];
        __half h = __float2half_rn(v);
        __half l = __float2half_rn(v - __half2float(h));
        g_bext[(size_t)n * KE_ + k]      = h;
        g_bext[(size_t)n * KE_ + D_ + k] = l;
    }
}

// ---------------- unified GEMM: 12 pair-iters, stage [Ah|Al|Bh], 64x64 warp tiles ----------------
#define NP    12
#define TILEB 16384
#define STB   (3*TILEB)
#define PITCH 132
#define SMEM_REQ (2*STB + 1024)

__global__ __launch_bounds__(128, 2)
void gemm_all(const float* __restrict__ Wb, float* __restrict__ resid)
{
    extern __shared__ char dsm[];
    __shared__ __align__(16) float s_bias[128];
    __shared__ int s_gi[128];
    __shared__ int s_slot[128];

    char* smem_al = (char*)(((uintptr_t)dsm + 1023) & ~(uintptr_t)1023);
    const uint32_t sbase = smem_u32(smem_al);

    const int bid = blockIdx.x;
    const bool isq = bid < 768;
    int n0, m0, limit;
    const char* agbase;
    const int tid = threadIdx.x;

    if (isq) {
        int by = bid / 6;
        if (by >= g_ntilesq[0]) return;
        n0 = (bid % 6) * 128;
        m0 = by * 128;
        limit = g_mcq[0];
        agbase = (const char*)g_apool + (size_t)m0 * (KE_ * 2);
        int idx = m0 + tid;
        s_gi[tid] = g_gidxq[idx < B_*P_ ? idx : 0];
    } else {
        int r = bid - 768;
        int by = r / 12;
        if (by >= g_ntiles[0]) return;
        n0 = 768 + (r % 12) * 128;
        m0 = by * 128;
        limit = g_mc[0];
        agbase = (const char*)g_aextc + (size_t)m0 * (KE_ * 2);
        int m = g_gidx[m0 + tid];
        s_gi[tid] = m >> 9;            // batch
        s_slot[tid] = g_lp[m];         // local slot
    }
    const char* bgbase = (const char*)g_bext + (size_t)n0 * (KE_ * 2);

    const int wid = tid >> 5, lane = tid & 31;
    const int wm = wid & 1, wn = wid >> 1;

    s_bias[tid] = Wb[n0 + tid];

    uint32_t ld_off[8];
    int g_offv[8];
    #pragma unroll
    for (int p = 0; p < 8; p++) {
        int idx = p * 128 + tid;
        int row = idx >> 3, seg = (idx & 7) * 16;
        ld_off[p] = SWZ128(row * 128 + seg);
        g_offv[p] = row * (KE_ * 2) + seg;
    }

    auto issue = [&](int j) {
        const char* ah = agbase + j * 128;
        const char* al = agbase + 1536 + j * 128;
        const char* bh = bgbase + j * 128;
        uint32_t base = sbase + (j & 1) * STB;
        #pragma unroll
        for (int p = 0; p < 8; p++)
            cp_async16(base + ld_off[p], ah + g_offv[p]);
        #pragma unroll
        for (int p = 0; p < 8; p++)
            cp_async16(base + TILEB + ld_off[p], al + g_offv[p]);
        #pragma unroll
        for (int p = 0; p < 8; p++)
            cp_async16(base + 2 * TILEB + ld_off[p], bh + g_offv[p]);
        cp_commit();
    };

    float c[4][8][4];
    #pragma unroll
    for (int i = 0; i < 4; i++)
        #pragma unroll
        for (int j = 0; j < 8; j++)
            #pragma unroll
            for (int q = 0; q < 4; q++) c[i][j][q] = 0.0f;

    uint32_t a_off[4][4], b_off[4][4];
    #pragma unroll
    for (int mi = 0; mi < 4; mi++)
        #pragma unroll
        for (int ks = 0; ks < 4; ks++) {
            int r = wm * 64 + mi * 16 + (lane & 15);
            int cb = ks * 32 + (lane >> 4) * 16;
            a_off[mi][ks] = SWZ128(r * 128 + cb);
        }
    #pragma unroll
    for (int ni = 0; ni < 4; ni++)
        #pragma unroll
        for (int ks = 0; ks < 4; ks++) {
            int r = wn * 64 + ni * 16 + (lane & 7) + ((lane >> 4) << 3);
            int cb = ks * 32 + ((lane >> 3) & 1) * 16;
            b_off[ni][ks] = 2 * TILEB + SWZ128(r * 128 + cb);
        }

    issue(0);

    for (int j = 0; j < NP; j++) {
        if (j + 1 < NP) { issue(j + 1); cp_wait<1>(); }
        else cp_wait<0>();
        __syncthreads();

        uint32_t buf = sbase + (j & 1) * STB;
        #pragma unroll
        for (int ks = 0; ks < 4; ks++) {
            uint32_t bb[4][4];
            #pragma unroll
            for (int ni = 0; ni < 4; ni++)
                ldsm4(bb[ni], buf + b_off[ni][ks]);
            uint32_t av[4][4];
            #pragma unroll
            for (int mi = 0; mi < 4; mi++)
                ldsm4(av[mi], buf + a_off[mi][ks]);
            #pragma unroll
            for (int ni = 0; ni < 4; ni++)
                #pragma unroll
                for (int mi = 0; mi < 4; mi++) {
                    mma16816(c[mi][2 * ni],     av[mi], bb[ni][0], bb[ni][1]);
                    mma16816(c[mi][2 * ni + 1], av[mi], bb[ni][2], bb[ni][3]);
                }
            #pragma unroll
            for (int mi = 0; mi < 4; mi++)
                ldsm4(av[mi], buf + TILEB + a_off[mi][ks]);
            #pragma unroll
            for (int ni = 0; ni < 4; ni++)
                #pragma unroll
                for (int mi = 0; mi < 4; mi++) {
                    mma16816(c[mi][2 * ni],     av[mi], bb[ni][0], bb[ni][1]);
                    mma16816(c[mi][2 * ni + 1], av[mi], bb[ni][2], bb[ni][3]);
                }
        }
        __syncthreads();
    }

    // ---- stage C to smem ----
    float* Csm = (float*)smem_al;
    #pragma unroll
    for (int mi = 0; mi < 4; mi++)
        #pragma unroll
        for (int nj = 0; nj < 8; nj++) {
            int row = wm * 64 + mi * 16 + (lane >> 2);
            int col = wn * 64 + nj * 8 + (lane & 3) * 2;
            *(float2*)&Csm[row * PITCH + col]       = make_float2(c[mi][nj][0], c[mi][nj][1]);
            *(float2*)&Csm[(row + 8) * PITCH + col] = make_float2(c[mi][nj][2], c[mi][nj][3]);
        }
    __syncthreads();

    const int row = tid;
    if (m0 + row < limit) {
        if (isq) {
            int pr = s_gi[row];
            float* dst = resid + (size_t)pr * D_ + n0;
            #pragma unroll
            for (int i = 0; i < 32; i++) {
                float4 x = *(float4*)&Csm[row * PITCH + i * 4];
                float4 bi = *(float4*)&s_bias[i * 4];
                *(float4*)(dst + i * 4) = make_float4(x.x + bi.x, x.y + bi.y,
                                                      x.z + bi.z, x.w + bi.w);
            }
        } else {
            int b = s_gi[row];
            int slot = s_slot[row];
            int region = 1 + (n0 >= 2 * D_);
            int head0 = (n0 - region * D_) >> 6;
            __half* g = (region == 1) ? g_k : g_v;
            #pragma unroll
            for (int half = 0; half < 2; half++) {
                int cbase = half * 64;
                __half* dst = g + (((size_t)(b * H_ + head0 + half)) * S_ + slot) * DH_;
                #pragma unroll
                for (int i = 0; i < 16; i++) {
                    float4 x = *(float4*)&Csm[row * PITCH + cbase + i * 4];
                    float4 bi = *(float4*)&s_bias[cbase + i * 4];
                    uint2 o;
                    o.x = cvt_f16x2(x.y + bi.y, x.x + bi.x);
                    o.y = cvt_f16x2(x.w + bi.w, x.z + bi.z);
                    *(uint2*)(dst + i * 4) = o;
                }
            }
        }
    }
}

// ---------------- attention: FA2 mma.sync over COMPACTED K/V ----------------
__global__ __launch_bounds__(128)
void attn_mma(const int* __restrict__ maskp, const float* __restrict__ resid,
              float* __restrict__ out)
{
    __shared__ __align__(16) uint8_t sKV[3][8192];
    __shared__ float sfo[512];

    const int tid = threadIdx.x;
    const int lane = tid & 31, w = tid >> 5;
    const int b = blockIdx.z, h = blockIdx.y;
    const int p0 = blockIdx.x * 128 + w * 32;

    const float slope = (h < 8) ? exp2f(-(float)(h + 1)) : exp2f(-0.5f - (float)(h - 8));
    const uint32_t sbase = smem_u32(sKV);

    const int cnt = g_cnt[b];
    const int boff = g_boff[b];
    const int nch = (cnt + 31) >> 5;

    #pragma unroll
    for (int i = 0; i < 4; i++) {
        int idx = tid * 4 + i;
        sfo[idx] = (idx < cnt) ? (float)(g_gidx[boff + idx] - b * S_) : 1.0e6f;
    }

    uint32_t qh[2][4][4], ql[2][4][4];
    {
        const float* qb = resid + (size_t)(b * P_) * D_ + h * 64;
        #pragma unroll
        for (int mi = 0; mi < 2; mi++)
            #pragma unroll
            for (int ks = 0; ks < 4; ks++) {
                int r0 = p0 + mi * 16 + (lane >> 2);
                int c0 = ks * 16 + (lane & 3) * 2;
                float2 v[4];
                v[0] = *(const float2*)(qb + (size_t)r0 * D_ + c0);
                v[1] = *(const float2*)(qb + (size_t)(r0 + 8) * D_ + c0);
                v[2] = *(const float2*)(qb + (size_t)r0 * D_ + c0 + 8);
                v[3] = *(const float2*)(qb + (size_t)(r0 + 8) * D_ + c0 + 8);
                #pragma unroll
                for (int j = 0; j < 4; j++) {
                    uint32_t hp = cvt_f16x2(v[j].y, v[j].x);
                    float2 hf = unpack_h2(hp);
                    qh[mi][ks][j] = hp;
                    ql[mi][ks][j] = cvt_f16x2(v[j].y - hf.y, v[j].x - hf.x);
                }
            }
    }

    uint32_t kbo[4], vbo[4];
    {
        int rk = (lane & 7) + ((lane >> 4) << 3);
        int rv = ((lane >> 3) & 1) * 8 + (lane & 7);
        #pragma unroll
        for (int ks = 0; ks < 4; ks++)
            kbo[ks] = SWZ128(rk * 128 + ks * 32 + ((lane >> 3) & 1) * 16);
        #pragma unroll
        for (int d16 = 0; d16 < 4; d16++)
            vbo[d16] = SWZ128(rv * 128 + d16 * 32 + ((lane >> 4) & 1) * 16);
    }

    float o[2][8][4];
    #pragma unroll
    for (int mi = 0; mi < 2; mi++)
        #pragma unroll
        for (int j = 0; j < 8; j++)
            #pragma unroll
            for (int q = 0; q < 4; q++) o[mi][j][q] = 0.0f;
    float mrun[2][2] = {{-1e30f, -1e30f}, {-1e30f, -1e30f}};
    float lsum[2][2] = {{0.0f, 0.0f}, {0.0f, 0.0f}};

    const __half* kg = g_k + (size_t)(b * H_ + h) * S_ * DH_;
    const __half* vg = g_v + (size_t)(b * H_ + h) * S_ * DH_;

    const int ldrow = tid >> 2;
    const int ldc   = (tid & 3) * 32;

    auto issueKV = [&](int cc) {
        int stage = cc - (cc / 3) * 3;
        uint32_t base = sbase + stage * 8192;
        const char* ks = (const char*)(kg + (size_t)(cc * 32 + ldrow) * 64) + ldc;
        const char* vs = (const char*)(vg + (size_t)(cc * 32 + ldrow) * 64) + ldc;
        #pragma unroll
        for (int i = 0; i < 2; i++) {
            uint32_t off = SWZ128(ldrow * 128 + ldc + i * 16);
            cp_async16(base + off, ks + i * 16);
            cp_async16(base + 4096 + off, vs + i * 16);
        }
        cp_commit();
    };

    issueKV(0);
    if (nch > 1) issueKV(1);

    for (int cc = 0; cc < nch; cc++) {
        const int s0 = cc * 32;
        if (cc + 2 < nch) { cp_wait<1>(); } else { cp_wait<0>(); }
        __syncthreads();
        int stage = cc - (cc / 3) * 3;
        const uint32_t k_base = sbase + stage * 8192;
        const uint32_t v_base = k_base + 4096;

        float sc[2][4][4];
        #pragma unroll
        for (int mi = 0; mi < 2; mi++)
            #pragma unroll
            for (int j = 0; j < 4; j++)
                #pragma unroll
                for (int q = 0; q < 4; q++) sc[mi][j][q] = 0.0f;

        #pragma unroll
        for (int n16 = 0; n16 < 2; n16++) {
            #pragma unroll
            for (int ks = 0; ks < 4; ks++) {
                uint32_t bh4[4];
                ldsm4(bh4, k_base + n16 * 2048 + kbo[ks]);
                #pragma unroll
                for (int mi = 0; mi < 2; mi++) {
                    mma16816(sc[mi][2*n16],   qh[mi][ks], bh4[0], bh4[1]);
                    mma16816(sc[mi][2*n16],   ql[mi][ks], bh4[0], bh4[1]);
                    mma16816(sc[mi][2*n16+1], qh[mi][ks], bh4[2], bh4[3]);
                    mma16816(sc[mi][2*n16+1], ql[mi][ks], bh4[2], bh4[3]);
                }
            }
        }

        #pragma unroll
        for (int mi = 0; mi < 2; mi++) {
            float r0f = (float)(p0 + mi * 16 + (lane >> 2));
            float r1f = r0f + 8.0f;
            float mx0 = -1e30f, mx1 = -1e30f;
            #pragma unroll
            for (int n8 = 0; n8 < 4; n8++) {
                int cl = s0 + n8 * 8 + (lane & 3) * 2;
                float c0f = sfo[cl], c1f = sfo[cl + 1];
                sc[mi][n8][0] = sc[mi][n8][0] * 0.125f - slope * fabsf(c0f - r0f);
                sc[mi][n8][1] = sc[mi][n8][1] * 0.125f - slope * fabsf(c1f - r0f);
                sc[mi][n8][2] = sc[mi][n8][2] * 0.125f - slope * fabsf(c0f - r1f);
                sc[mi][n8][3] = sc[mi][n8][3] * 0.125f - slope * fabsf(c1f - r1f);
                mx0 = fmaxf(mx0, fmaxf(sc[mi][n8][0], sc[mi][n8][1]));
                mx1 = fmaxf(mx1, fmaxf(sc[mi][n8][2], sc[mi][n8][3]));
            }
            mx0 = fmaxf(mx0, __shfl_xor_sync(0xffffffffu, mx0, 1));
            mx0 = fmaxf(mx0, __shfl_xor_sync(0xffffffffu, mx0, 2));
            mx1 = fmaxf(mx1, __shfl_xor_sync(0xffffffffu, mx1, 1));
            mx1 = fmaxf(mx1, __shfl_xor_sync(0xffffffffu, mx1, 2));
            float mn0 = fmaxf(mrun[mi][0], mx0);
            float mn1 = fmaxf(mrun[mi][1], mx1);
            float cr0 = __expf(mrun[mi][0] - mn0);
            float cr1 = __expf(mrun[mi][1] - mn1);
            mrun[mi][0] = mn0; mrun[mi][1] = mn1;
            float rs0 = 0.0f, rs1 = 0.0f;
            #pragma unroll
            for (int n8 = 0; n8 < 4; n8++) {
                sc[mi][n8][0] = __expf(sc[mi][n8][0] - mn0);
                sc[mi][n8][1] = __expf(sc[mi][n8][1] - mn0);
                sc[mi][n8][2] = __expf(sc[mi][n8][2] - mn1);
                sc[mi][n8][3] = __expf(sc[mi][n8][3] - mn1);
                rs0 += sc[mi][n8][0] + sc[mi][n8][1];
                rs1 += sc[mi][n8][2] + sc[mi][n8][3];
            }
            rs0 += __shfl_xor_sync(0xffffffffu, rs0, 1);
            rs0 += __shfl_xor_sync(0xffffffffu, rs0, 2);
            rs1 += __shfl_xor_sync(0xffffffffu, rs1, 1);
            rs1 += __shfl_xor_sync(0xffffffffu, rs1, 2);
            lsum[mi][0] = lsum[mi][0] * cr0 + rs0;
            lsum[mi][1] = lsum[mi][1] * cr1 + rs1;
            #pragma unroll
            for (int d8 = 0; d8 < 8; d8++) {
                o[mi][d8][0] *= cr0; o[mi][d8][1] *= cr0;
                o[mi][d8][2] *= cr1; o[mi][d8][3] *= cr1;
            }
        }

        #pragma unroll
        for (int ksP = 0; ksP < 2; ksP++) {
            uint32_t ph[2][4], pl[2][4];
            #pragma unroll
            for (int mi = 0; mi < 2; mi++) {
                float e0 = sc[mi][2*ksP][0], e1 = sc[mi][2*ksP][1];
                float e2 = sc[mi][2*ksP][2], e3 = sc[mi][2*ksP][3];
                float f0 = sc[mi][2*ksP+1][0], f1 = sc[mi][2*ksP+1][1];
                float f2 = sc[mi][2*ksP+1][2], f3 = sc[mi][2*ksP+1][3];
                ph[mi][0] = cvt_f16x2(e1, e0);
                ph[mi][1] = cvt_f16x2(e3, e2);
                ph[mi][2] = cvt_f16x2(f1, f0);
                ph[mi][3] = cvt_f16x2(f3, f2);
                float2 g0 = unpack_h2(ph[mi][0]);
                float2 g1 = unpack_h2(ph[mi][1]);
                float2 g2 = unpack_h2(ph[mi][2]);
                float2 g3 = unpack_h2(ph[mi][3]);
                pl[mi][0] = cvt_f16x2(e1 - g0.y, e0 - g0.x);
                pl[mi][1] = cvt_f16x2(e3 - g1.y, e2 - g1.x);
                pl[mi][2] = cvt_f16x2(f1 - g2.y, f0 - g2.x);
                pl[mi][3] = cvt_f16x2(f3 - g3.y, f2 - g3.x);
            }
            #pragma unroll
            for (int d16 = 0; d16 < 4; d16++) {
                uint32_t vh4[4];
                ldsm4t(vh4, v_base + ksP * 2048 + vbo[d16]);
                #pragma unroll
                for (int mi = 0; mi < 2; mi++) {
                    mma16816(o[mi][2*d16],   ph[mi], vh4[0], vh4[1]);
                    mma16816(o[mi][2*d16],   pl[mi], vh4[0], vh4[1]);
                    mma16816(o[mi][2*d16+1], ph[mi], vh4[2], vh4[3]);
                    mma16816(o[mi][2*d16+1], pl[mi], vh4[2], vh4[3]);
                }
            }
        }
        if (cc + 2 < nch) issueKV(cc + 2);
    }

    #pragma unroll
    for (int mi = 0; mi < 2; mi++) {
        int rp0 = p0 + mi * 16 + (lane >> 2);
        int rp1 = rp0 + 8;
        int nm0 = maskp[b * S_ + 2 * rp0] | maskp[b * S_ + 2 * rp0 + 1];
        int nm1 = maskp[b * S_ + 2 * rp1] | maskp[b * S_ + 2 * rp1 + 1];
        float s0v = nm0 ? (1.0f / lsum[mi][0]) : 0.0f;
        float s1v = nm1 ? (1.0f / lsum[mi][1]) : 0.0f;
        float* dst0 = out + (size_t)(b * P_ + rp0) * D_ + h * 64 + (lane & 3) * 2;
        float* dst1 = out + (size_t)(b * P_ + rp1) * D_ + h * 64 + (lane & 3) * 2;
        #pragma unroll
        for (int d8 = 0; d8 < 8; d8++) {
            *(float2*)(dst0 + d8 * 8) = make_float2(o[mi][d8][0] * s0v, o[mi][d8][1] * s0v);
            *(float2*)(dst1 + d8 * 8) = make_float2(o[mi][d8][2] * s1v, o[mi][d8][3] * s1v);
        }
    }
}

// ---------------- launch ----------------
extern "C" void kernel_launch(void* const* d_in, const int* in_sizes, int n_in,
                              void* d_out, int out_size)
{
    const float* hidden = (const float*)d_in[0];
    const int*   mask   = (const int*)d_in[1];
    const float* W      = (const float*)d_in[2];
    const float* Wb     = (const float*)d_in[3];
    float* out = (float*)d_out;

    float* resid = out + RQ_OFF;
    float* nmout = out + NM_OFF;

    (void)cudaFuncSetAttribute(gemm_all, cudaFuncAttributeMaxDynamicSharedMemorySize, SMEM_REQ);

    scan_a<<<B_, 512>>>(mask, nmout);
    scan_b<<<1, 1>>>();
    scatter_idx<<<B_, 512>>>(mask);
    split_hidden<<<B_ * P_, 192>>>(hidden, mask, resid);
    split_wT<<<dim3(N3_/32, D_/32), dim3(32, 8)>>>(W);
    gemm_all<<<768 + 12*256, 128, SMEM_REQ>>>(Wb, resid);
    attn_mma<<<dim3(2, H_, B_), 128>>>(mask, resid, out);
}

// round 16
// speedup vs baseline: 1.0994x; 1.0039x over previous
#include <cuda_runtime.h>
#include <cuda_fp16.h>
#include <cstdint>

// Problem constants
#define B_   64
#define S_   512
#define D_   768
#define H_   12
#define DH_  64
#define P_   256
#define N3_  2304
#define KE_  1536   // stored extended K (hi 768 | lo 768), fp16

#define ATTN_SZ   (B_*P_*D_)
#define NM_OFF    (ATTN_SZ)
#define RQ_OFF    (ATTN_SZ + B_*P_)

// Scratch. K/V compacted per (b,h): local slot < cnt[b]; rest stay zero.
__device__ __half g_k[B_*H_*S_*DH_];
__device__ __half g_v[B_*H_*S_*DH_];
__device__ __half g_aextc[B_*S_*KE_];    // globally compacted unmasked rows, hi|lo
__device__ __half g_apool[B_*P_*KE_];    // globally compacted pooled (nm=1) rows, hi|lo
__device__ __half g_bext[N3_*KE_];       // [2304][1536]  W^T hi|lo
// compaction bookkeeping
__device__ int g_cnt[B_];
__device__ int g_lp[B_*S_];
__device__ int g_boff[B_];
__device__ int g_mc[1];
__device__ int g_ntiles[1];
__device__ int g_gidx[B_*S_ + 128];
// pooled-q compaction
__device__ int g_cntq[B_];
__device__ int g_lpq[B_*P_];
__device__ int g_boffq[B_];
__device__ int g_mcq[1];
__device__ int g_ntilesq[1];
__device__ int g_gidxq[B_*P_];

// ---------------- PTX helpers ----------------
__device__ __forceinline__ uint32_t smem_u32(const void* p) {
    uint32_t a;
    asm("{ .reg .u64 t; cvta.to.shared.u64 t, %1; cvt.u32.u64 %0, t; }" : "=r"(a) : "l"(p));
    return a;
}
#define SWZ128(o) ((o) ^ (((o) >> 3) & 0x70))

__device__ __forceinline__ void cp_async16(uint32_t dst, const void* src) {
    asm volatile("cp.async.cg.shared.global [%0], [%1], 16;" :: "r"(dst), "l"(src) : "memory");
}
__device__ __forceinline__ void cp_commit() {
    asm volatile("cp.async.commit_group;" ::: "memory");
}
template<int N>
__device__ __forceinline__ void cp_wait() {
    asm volatile("cp.async.wait_group %0;" :: "n"(N) : "memory");
}
__device__ __forceinline__ void ldsm4(uint32_t* r, uint32_t addr) {
    asm volatile("ldmatrix.sync.aligned.m8n8.x4.shared.b16 {%0,%1,%2,%3}, [%4];"
        : "=r"(r[0]), "=r"(r[1]), "=r"(r[2]), "=r"(r[3]) : "r"(addr));
}
__device__ __forceinline__ void ldsm4t(uint32_t* r, uint32_t addr) {
    asm volatile("ldmatrix.sync.aligned.m8n8.x4.trans.shared.b16 {%0,%1,%2,%3}, [%4];"
        : "=r"(r[0]), "=r"(r[1]), "=r"(r[2]), "=r"(r[3]) : "r"(addr));
}
__device__ __forceinline__ void mma16816(float* c, const uint32_t* a, uint32_t b0, uint32_t b1) {
    asm volatile("mma.sync.aligned.m16n8k16.row.col.f32.f16.f16.f32 "
        "{%0,%1,%2,%3}, {%4,%5,%6,%7}, {%8,%9}, {%0,%1,%2,%3};"
        : "+f"(c[0]), "+f"(c[1]), "+f"(c[2]), "+f"(c[3])
        : "r"(a[0]), "r"(a[1]), "r"(a[2]), "r"(a[3]), "r"(b0), "r"(b1));
}
__device__ __forceinline__ uint32_t cvt_f16x2(float hi, float lo) {
    uint32_t r;
    asm("cvt.rn.f16x2.f32 %0, %1, %2;" : "=r"(r) : "f"(hi), "f"(lo));
    return r;
}
__device__ __forceinline__ float2 unpack_h2(uint32_t u) {
    __half2 h = *reinterpret_cast<__half2*>(&u);
    return make_float2(__low2float(h), __high2float(h));
}
__device__ __forceinline__ void split4(float4 a, uint2& ph, uint2& pl) {
    __half h0 = __float2half_rn(a.x), h1 = __float2half_rn(a.y);
    __half h2 = __float2half_rn(a.z), h3 = __float2half_rn(a.w);
    __half l0 = __float2half_rn(a.x - __half2float(h0));
    __half l1 = __float2half_rn(a.y - __half2float(h1));
    __half l2 = __float2half_rn(a.z - __half2float(h2));
    __half l3 = __float2half_rn(a.w - __half2float(h3));
    ph.x = (uint32_t)__half_as_ushort(h0) | ((uint32_t)__half_as_ushort(h1) << 16);
    ph.y = (uint32_t)__half_as_ushort(h2) | ((uint32_t)__half_as_ushort(h3) << 16);
    pl.x = (uint32_t)__half_as_ushort(l0) | ((uint32_t)__half_as_ushort(l1) << 16);
    pl.y = (uint32_t)__half_as_ushort(l2) | ((uint32_t)__half_as_ushort(l3) << 16);
}

// ---------------- scan: per-batch prefixes (kv + pooled) + new_mask ----------------
__global__ __launch_bounds__(512)
void scan_a(const int* __restrict__ mask, float* __restrict__ out_nm)
{
    __shared__ int wsum[16], woff[16];
    __shared__ int wsumq[8], woffq[8];
    int b = blockIdx.x, s = threadIdx.x;
    int lane = s & 31, w = s >> 5;

    int v = mask[b * S_ + s] != 0;
    unsigned bal = __ballot_sync(0xffffffffu, v);
    int wpre = __popc(bal & ((1u << lane) - 1u));
    if (lane == 31) wsum[w] = __popc(bal);

    int nm = 0, wpreq = 0;
    if (s < 256) {
        nm = (mask[b * S_ + 2 * s] | mask[b * S_ + 2 * s + 1]) != 0;
        out_nm[b * P_ + s] = (float)nm;
    }
    unsigned balq = __ballot_sync(0xffffffffu, nm);
    if (w < 8) {
        wpreq = __popc(balq & ((1u << lane) - 1u));
        if (lane == 31) wsumq[w] = __popc(balq);
    }
    __syncthreads();
    if (s == 0) {
        int acc = 0;
        #pragma unroll
        for (int i = 0; i < 16; i++) { woff[i] = acc; acc += wsum[i]; }
        g_cnt[b] = acc;
        int accq = 0;
        #pragma unroll
        for (int i = 0; i < 8; i++) { woffq[i] = accq; accq += wsumq[i]; }
        g_cntq[b] = accq;
    }
    __syncthreads();
    if (v) g_lp[b * S_ + s] = woff[w] + wpre;
    if (s < 256 && nm) g_lpq[b * P_ + s] = woffq[w] + wpreq;
}

__global__ void scan_b()
{
    int acc = 0, accq = 0;
    for (int i = 0; i < B_; i++) {
        g_boff[i] = acc;   acc += g_cnt[i];
        g_boffq[i] = accq; accq += g_cntq[i];
    }
    g_mc[0] = acc;
    g_mcq[0] = accq;
    int nt = (acc + 127) >> 7;
    g_ntiles[0] = nt;
    g_ntilesq[0] = (accq + 127) >> 7;
    int pad = nt * 128;
    for (int i = acc; i < pad; i++) g_gidx[i] = 0;
}

// ---------------- fused hidden split (also scatters g_gidx / g_gidxq) ----------------
__global__ __launch_bounds__(192)
void split_hidden(const float* __restrict__ A, const int* __restrict__ mask,
                  float* __restrict__ resid)
{
    int pr = blockIdx.x;                       // 0..16383
    int b = pr >> 8;
    int m0 = b * S_ + ((pr & 255) << 1);
    int k4 = threadIdx.x * 4;

    int mk0 = mask[m0], mk1 = mask[m0 + 1];
    float4 a0 = *(const float4*)&A[(size_t)m0 * D_ + k4];
    float4 a1 = *(const float4*)&A[(size_t)(m0 + 1) * D_ + k4];

    if (mk0 | mk1) {
        float f0 = (float)mk0, f1 = (float)mk1;
        float inv = 1.0f / fmaxf(f0 + f1, 1.0f);
        float4 ap = make_float4((f0 * a0.x + f1 * a1.x) * inv,
                                (f0 * a0.y + f1 * a1.y) * inv,
                                (f0 * a0.z + f1 * a1.z) * inv,
                                (f0 * a0.w + f1 * a1.w) * inv);
        uint2 ph, pl; split4(ap, ph, pl);
        size_t qi = (size_t)g_boffq[b] + g_lpq[pr];
        *(uint2*)&g_apool[qi * KE_ + k4]      = ph;
        *(uint2*)&g_apool[qi * KE_ + D_ + k4] = pl;
        if (threadIdx.x == 0) g_gidxq[qi] = pr;
    } else {
        // residual_query row is exactly zero; output buffer is poisoned -> write it
        *(float4*)&resid[(size_t)pr * D_ + k4] = make_float4(0.f, 0.f, 0.f, 0.f);
    }

    int boff = g_boff[b];
    if (mk0) {
        size_t ci = (size_t)boff + g_lp[m0];
        uint2 h, l; split4(a0, h, l);
        *(uint2*)&g_aextc[ci * KE_ + k4]      = h;
        *(uint2*)&g_aextc[ci * KE_ + D_ + k4] = l;
        if (threadIdx.x == 0) g_gidx[ci] = m0;
    }
    if (mk1) {
        size_t ci = (size_t)boff + g_lp[m0 + 1];
        uint2 h, l; split4(a1, h, l);
        *(uint2*)&g_aextc[ci * KE_ + k4]      = h;
        *(uint2*)&g_aextc[ci * KE_ + D_ + k4] = l;
        if (threadIdx.x == 0) g_gidx[ci] = m0 + 1;
    }
}

// ---------------- Prepass W: transpose + split ----------------
__global__ __launch_bounds__(256)
void split_wT(const float* __restrict__ W)
{
    __shared__ float t[32][33];
    int n0 = blockIdx.x * 32, k0 = blockIdx.y * 32;
    int tx = threadIdx.x, ty = threadIdx.y;
    #pragma unroll
    for (int j = 0; j < 4; j++)
        t[ty + j * 8][tx] = W[(size_t)(k0 + ty + j * 8) * N3_ + n0 + tx];
    __syncthreads();
    #pragma unroll
    for (int j = 0; j < 4; j++) {
        int n = n0 + ty + j * 8;
        int k = k0 + tx;
        float v = t[tx][ty + j * 8];
        __half h = __float2half_rn(v);
        __half l = __float2half_rn(v - __half2float(h));
        g_bext[(size_t)n * KE_ + k]      = h;
        g_bext[(size_t)n * KE_ + D_ + k] = l;
    }
}

// ---------------- unified GEMM: 12 pair-iters, stage [Ah|Al|Bh], 64x64 warp tiles ----------------
// Single barrier per iteration: cp_wait; barrier (proves compute(j-1) done by all); issue(j+1); compute(j).
#define NP    12
#define TILEB 16384
#define STB   (3*TILEB)
#define PITCH 132
#define SMEM_REQ (2*STB + 1024)

__global__ __launch_bounds__(128, 2)
void gemm_all(const float* __restrict__ Wb, float* __restrict__ resid)
{
    extern __shared__ char dsm[];
    __shared__ __align__(16) float s_bias[128];
    __shared__ int s_gi[128];
    __shared__ int s_slot[128];

    char* smem_al = (char*)(((uintptr_t)dsm + 1023) & ~(uintptr_t)1023);
    const uint32_t sbase = smem_u32(smem_al);

    const int bid = blockIdx.x;
    const bool isq = bid < 768;
    int n0, m0, limit;
    const char* agbase;
    const int tid = threadIdx.x;

    if (isq) {
        int by = bid / 6;
        if (by >= g_ntilesq[0]) return;
        n0 = (bid % 6) * 128;
        m0 = by * 128;
        limit = g_mcq[0];
        agbase = (const char*)g_apool + (size_t)m0 * (KE_ * 2);
        int idx = m0 + tid;
        s_gi[tid] = g_gidxq[idx < B_*P_ ? idx : 0];
    } else {
        int r = bid - 768;
        int by = r / 12;
        if (by >= g_ntiles[0]) return;
        n0 = 768 + (r % 12) * 128;
        m0 = by * 128;
        limit = g_mc[0];
        agbase = (const char*)g_aextc + (size_t)m0 * (KE_ * 2);
        int m = g_gidx[m0 + tid];
        s_gi[tid] = m >> 9;            // batch
        s_slot[tid] = g_lp[m];         // local slot
    }
    const char* bgbase = (const char*)g_bext + (size_t)n0 * (KE_ * 2);

    const int wid = tid >> 5, lane = tid & 31;
    const int wm = wid & 1, wn = wid >> 1;

    s_bias[tid] = Wb[n0 + tid];

    uint32_t ld_off[8];
    int g_offv[8];
    #pragma unroll
    for (int p = 0; p < 8; p++) {
        int idx = p * 128 + tid;
        int row = idx >> 3, seg = (idx & 7) * 16;
        ld_off[p] = SWZ128(row * 128 + seg);
        g_offv[p] = row * (KE_ * 2) + seg;
    }

    auto issue = [&](int j) {
        const char* ah = agbase + j * 128;
        const char* al = agbase + 1536 + j * 128;
        const char* bh = bgbase + j * 128;
        uint32_t base = sbase + (j & 1) * STB;
        #pragma unroll
        for (int p = 0; p < 8; p++)
            cp_async16(base + ld_off[p], ah + g_offv[p]);
        #pragma unroll
        for (int p = 0; p < 8; p++)
            cp_async16(base + TILEB + ld_off[p], al + g_offv[p]);
        #pragma unroll
        for (int p = 0; p < 8; p++)
            cp_async16(base + 2 * TILEB + ld_off[p], bh + g_offv[p]);
        cp_commit();
    };

    float c[4][8][4];
    #pragma unroll
    for (int i = 0; i < 4; i++)
        #pragma unroll
        for (int j = 0; j < 8; j++)
            #pragma unroll
            for (int q = 0; q < 4; q++) c[i][j][q] = 0.0f;

    uint32_t a_off[4][4], b_off[4][4];
    #pragma unroll
    for (int mi = 0; mi < 4; mi++)
        #pragma unroll
        for (int ks = 0; ks < 4; ks++) {
            int r = wm * 64 + mi * 16 + (lane & 15);
            int cb = ks * 32 + (lane >> 4) * 16;
            a_off[mi][ks] = SWZ128(r * 128 + cb);
        }
    #pragma unroll
    for (int ni = 0; ni < 4; ni++)
        #pragma unroll
        for (int ks = 0; ks < 4; ks++) {
            int r = wn * 64 + ni * 16 + (lane & 7) + ((lane >> 4) << 3);
            int cb = ks * 32 + ((lane >> 3) & 1) * 16;
            b_off[ni][ks] = 2 * TILEB + SWZ128(r * 128 + cb);
        }

    issue(0);

    for (int j = 0; j < NP; j++) {
        cp_wait<0>();
        __syncthreads();              // data ready + all warps done with buffer (j+1)&1
        if (j + 1 < NP) issue(j + 1);

        uint32_t buf = sbase + (j & 1) * STB;
        #pragma unroll
        for (int ks = 0; ks < 4; ks++) {
            uint32_t bb[4][4];
            #pragma unroll
            for (int ni = 0; ni < 4; ni++)
                ldsm4(bb[ni], buf + b_off[ni][ks]);
            uint32_t av[4][4];
            #pragma unroll
            for (int mi = 0; mi < 4; mi++)
                ldsm4(av[mi], buf + a_off[mi][ks]);
            #pragma unroll
            for (int ni = 0; ni < 4; ni++)
                #pragma unroll
                for (int mi = 0; mi < 4; mi++) {
                    mma16816(c[mi][2 * ni],     av[mi], bb[ni][0], bb[ni][1]);
                    mma16816(c[mi][2 * ni + 1], av[mi], bb[ni][2], bb[ni][3]);
                }
            #pragma unroll
            for (int mi = 0; mi < 4; mi++)
                ldsm4(av[mi], buf + TILEB + a_off[mi][ks]);
            #pragma unroll
            for (int ni = 0; ni < 4; ni++)
                #pragma unroll
                for (int mi = 0; mi < 4; mi++) {
                    mma16816(c[mi][2 * ni],     av[mi], bb[ni][0], bb[ni][1]);
                    mma16816(c[mi][2 * ni + 1], av[mi], bb[ni][2], bb[ni][3]);
                }
        }
    }
    __syncthreads();   // all compute done before Csm staging overlays buffers

    // ---- stage C to smem ----
    float* Csm = (float*)smem_al;
    #pragma unroll
    for (int mi = 0; mi < 4; mi++)
        #pragma unroll
        for (int nj = 0; nj < 8; nj++) {
            int row = wm * 64 + mi * 16 + (lane >> 2);
            int col = wn * 64 + nj * 8 + (lane & 3) * 2;
            *(float2*)&Csm[row * PITCH + col]       = make_float2(c[mi][nj][0], c[mi][nj][1]);
            *(float2*)&Csm[(row + 8) * PITCH + col] = make_float2(c[mi][nj][2], c[mi][nj][3]);
        }
    __syncthreads();

    const int row = tid;
    if (m0 + row < limit) {
        if (isq) {
            int pr = s_gi[row];
            float* dst = resid + (size_t)pr * D_ + n0;
            #pragma unroll
            for (int i = 0; i < 32; i++) {
                float4 x = *(float4*)&Csm[row * PITCH + i * 4];
                float4 bi = *(float4*)&s_bias[i * 4];
                *(float4*)(dst + i * 4) = make_float4(x.x + bi.x, x.y + bi.y,
                                                      x.z + bi.z, x.w + bi.w);
            }
        } else {
            int b = s_gi[row];
            int slot = s_slot[row];
            int region = 1 + (n0 >= 2 * D_);
            int head0 = (n0 - region * D_) >> 6;
            __half* g = (region == 1) ? g_k : g_v;
            #pragma unroll
            for (int half = 0; half < 2; half++) {
                int cbase = half * 64;
                __half* dst = g + (((size_t)(b * H_ + head0 + half)) * S_ + slot) * DH_;
                #pragma unroll
                for (int i = 0; i < 16; i++) {
                    float4 x = *(float4*)&Csm[row * PITCH + cbase + i * 4];
                    float4 bi = *(float4*)&s_bias[cbase + i * 4];
                    uint2 o;
                    o.x = cvt_f16x2(x.y + bi.y, x.x + bi.x);
                    o.y = cvt_f16x2(x.w + bi.w, x.z + bi.z);
                    *(uint2*)(dst + i * 4) = o;
                }
            }
        }
    }
}

// ---------------- attention: FA2 mma.sync over COMPACTED K/V ----------------
__global__ __launch_bounds__(128)
void attn_mma(const int* __restrict__ maskp, const float* __restrict__ resid,
              float* __restrict__ out)
{
    __shared__ __align__(16) uint8_t sKV[3][8192];
    __shared__ float sfo[512];

    const int tid = threadIdx.x;
    const int lane = tid & 31, w = tid >> 5;
    const int b = blockIdx.z, h = blockIdx.y;
    const int p0 = blockIdx.x * 128 + w * 32;

    const float slope = (h < 8) ? exp2f(-(float)(h + 1)) : exp2f(-0.5f - (float)(h - 8));
    const uint32_t sbase = smem_u32(sKV);

    const int cnt = g_cnt[b];
    const int boff = g_boff[b];
    const int nch = (cnt + 31) >> 5;

    #pragma unroll
    for (int i = 0; i < 4; i++) {
        int idx = tid * 4 + i;
        sfo[idx] = (idx < cnt) ? (float)(g_gidx[boff + idx] - b * S_) : 1.0e6f;
    }

    uint32_t qh[2][4][4], ql[2][4][4];
    {
        const float* qb = resid + (size_t)(b * P_) * D_ + h * 64;
        #pragma unroll
        for (int mi = 0; mi < 2; mi++)
            #pragma unroll
            for (int ks = 0; ks < 4; ks++) {
                int r0 = p0 + mi * 16 + (lane >> 2);
                int c0 = ks * 16 + (lane & 3) * 2;
                float2 v[4];
                v[0] = *(const float2*)(qb + (size_t)r0 * D_ + c0);
                v[1] = *(const float2*)(qb + (size_t)(r0 + 8) * D_ + c0);
                v[2] = *(const float2*)(qb + (size_t)r0 * D_ + c0 + 8);
                v[3] = *(const float2*)(qb + (size_t)(r0 + 8) * D_ + c0 + 8);
                #pragma unroll
                for (int j = 0; j < 4; j++) {
                    uint32_t hp = cvt_f16x2(v[j].y, v[j].x);
                    float2 hf = unpack_h2(hp);
                    qh[mi][ks][j] = hp;
                    ql[mi][ks][j] = cvt_f16x2(v[j].y - hf.y, v[j].x - hf.x);
                }
            }
    }

    uint32_t kbo[4], vbo[4];
    {
        int rk = (lane & 7) + ((lane >> 4) << 3);
        int rv = ((lane >> 3) & 1) * 8 + (lane & 7);
        #pragma unroll
        for (int ks = 0; ks < 4; ks++)
            kbo[ks] = SWZ128(rk * 128 + ks * 32 + ((lane >> 3) & 1) * 16);
        #pragma unroll
        for (int d16 = 0; d16 < 4; d16++)
            vbo[d16] = SWZ128(rv * 128 + d16 * 32 + ((lane >> 4) & 1) * 16);
    }

    float o[2][8][4];
    #pragma unroll
    for (int mi = 0; mi < 2; mi++)
        #pragma unroll
        for (int j = 0; j < 8; j++)
            #pragma unroll
            for (int q = 0; q < 4; q++) o[mi][j][q] = 0.0f;
    float mrun[2][2] = {{-1e30f, -1e30f}, {-1e30f, -1e30f}};
    float lsum[2][2] = {{0.0f, 0.0f}, {0.0f, 0.0f}};

    const __half* kg = g_k + (size_t)(b * H_ + h) * S_ * DH_;
    const __half* vg = g_v + (size_t)(b * H_ + h) * S_ * DH_;

    const int ldrow = tid >> 2;
    const int ldc   = (tid & 3) * 32;

    auto issueKV = [&](int cc) {
        int stage = cc - (cc / 3) * 3;
        uint32_t base = sbase + stage * 8192;
        const char* ks = (const char*)(kg + (size_t)(cc * 32 + ldrow) * 64) + ldc;
        const char* vs = (const char*)(vg + (size_t)(cc * 32 + ldrow) * 64) + ldc;
        #pragma unroll
        for (int i = 0; i < 2; i++) {
            uint32_t off = SWZ128(ldrow * 128 + ldc + i * 16);
            cp_async16(base + off, ks + i * 16);
            cp_async16(base + 4096 + off, vs + i * 16);
        }
        cp_commit();
    };

    issueKV(0);
    if (nch > 1) issueKV(1);

    for (int cc = 0; cc < nch; cc++) {
        const int s0 = cc * 32;
        if (cc + 2 < nch) { cp_wait<1>(); } else { cp_wait<0>(); }
        __syncthreads();
        int stage = cc - (cc / 3) * 3;
        const uint32_t k_base = sbase + stage * 8192;
        const uint32_t v_base = k_base + 4096;

        float sc[2][4][4];
        #pragma unroll
        for (int mi = 0; mi < 2; mi++)
            #pragma unroll
            for (int j = 0; j < 4; j++)
                #pragma unroll
                for (int q = 0; q < 4; q++) sc[mi][j][q] = 0.0f;

        #pragma unroll
        for (int n16 = 0; n16 < 2; n16++) {
            #pragma unroll
            for (int ks = 0; ks < 4; ks++) {
                uint32_t bh4[4];
                ldsm4(bh4, k_base + n16 * 2048 + kbo[ks]);
                #pragma unroll
                for (int mi = 0; mi < 2; mi++) {
                    mma16816(sc[mi][2*n16],   qh[mi][ks], bh4[0], bh4[1]);
                    mma16816(sc[mi][2*n16],   ql[mi][ks], bh4[0], bh4[1]);
                    mma16816(sc[mi][2*n16+1], qh[mi][ks], bh4[2], bh4[3]);
                    mma16816(sc[mi][2*n16+1], ql[mi][ks], bh4[2], bh4[3]);
                }
            }
        }

        #pragma unroll
        for (int mi = 0; mi < 2; mi++) {
            float r0f = (float)(p0 + mi * 16 + (lane >> 2));
            float r1f = r0f + 8.0f;
            float mx0 = -1e30f, mx1 = -1e30f;
            #pragma unroll
            for (int n8 = 0; n8 < 4; n8++) {
                int cl = s0 + n8 * 8 + (lane & 3) * 2;
                float c0f = sfo[cl], c1f = sfo[cl + 1];
                sc[mi][n8][0] = sc[mi][n8][0] * 0.125f - slope * fabsf(c0f - r0f);
                sc[mi][n8][1] = sc[mi][n8][1] * 0.125f - slope * fabsf(c1f - r0f);
                sc[mi][n8][2] = sc[mi][n8][2] * 0.125f - slope * fabsf(c0f - r1f);
                sc[mi][n8][3] = sc[mi][n8][3] * 0.125f - slope * fabsf(c1f - r1f);
                mx0 = fmaxf(mx0, fmaxf(sc[mi][n8][0], sc[mi][n8][1]));
                mx1 = fmaxf(mx1, fmaxf(sc[mi][n8][2], sc[mi][n8][3]));
            }
            mx0 = fmaxf(mx0, __shfl_xor_sync(0xffffffffu, mx0, 1));
            mx0 = fmaxf(mx0, __shfl_xor_sync(0xffffffffu, mx0, 2));
            mx1 = fmaxf(mx1, __shfl_xor_sync(0xffffffffu, mx1, 1));
            mx1 = fmaxf(mx1, __shfl_xor_sync(0xffffffffu, mx1, 2));
            float mn0 = fmaxf(mrun[mi][0], mx0);
            float mn1 = fmaxf(mrun[mi][1], mx1);
            float cr0 = __expf(mrun[mi][0] - mn0);
            float cr1 = __expf(mrun[mi][1] - mn1);
            mrun[mi][0] = mn0; mrun[mi][1] = mn1;
            float rs0 = 0.0f, rs1 = 0.0f;
            #pragma unroll
            for (int n8 = 0; n8 < 4; n8++) {
                sc[mi][n8][0] = __expf(sc[mi][n8][0] - mn0);
                sc[mi][n8][1] = __expf(sc[mi][n8][1] - mn0);
                sc[mi][n8][2] = __expf(sc[mi][n8][2] - mn1);
                sc[mi][n8][3] = __expf(sc[mi][n8][3] - mn1);
                rs0 += sc[mi][n8][0] + sc[mi][n8][1];
                rs1 += sc[mi][n8][2] + sc[mi][n8][3];
            }
            rs0 += __shfl_xor_sync(0xffffffffu, rs0, 1);
            rs0 += __shfl_xor_sync(0xffffffffu, rs0, 2);
            rs1 += __shfl_xor_sync(0xffffffffu, rs1, 1);
            rs1 += __shfl_xor_sync(0xffffffffu, rs1, 2);
            lsum[mi][0] = lsum[mi][0] * cr0 + rs0;
            lsum[mi][1] = lsum[mi][1] * cr1 + rs1;
            #pragma unroll
            for (int d8 = 0; d8 < 8; d8++) {
                o[mi][d8][0] *= cr0; o[mi][d8][1] *= cr0;
                o[mi][d8][2] *= cr1; o[mi][d8][3] *= cr1;
            }
        }

        #pragma unroll
        for (int ksP = 0; ksP < 2; ksP++) {
            uint32_t ph[2][4], pl[2][4];
            #pragma unroll
            for (int mi = 0; mi < 2; mi++) {
                float e0 = sc[mi][2*ksP][0], e1 = sc[mi][2*ksP][1];
                float e2 = sc[mi][2*ksP][2], e3 = sc[mi][2*ksP][3];
                float f0 = sc[mi][2*ksP+1][0], f1 = sc[mi][2*ksP+1][1];
                float f2 = sc[mi][2*ksP+1][2], f3 = sc[mi][2*ksP+1][3];
                ph[mi][0] = cvt_f16x2(e1, e0);
                ph[mi][1] = cvt_f16x2(e3, e2);
                ph[mi][2] = cvt_f16x2(f1, f0);
                ph[mi][3] = cvt_f16x2(f3, f2);
                float2 g0 = unpack_h2(ph[mi][0]);
                float2 g1 = unpack_h2(ph[mi][1]);
                float2 g2 = unpack_h2(ph[mi][2]);
                float2 g3 = unpack_h2(ph[mi][3]);
                pl[mi][0] = cvt_f16x2(e1 - g0.y, e0 - g0.x);
                pl[mi][1] = cvt_f16x2(e3 - g1.y, e2 - g1.x);
                pl[mi][2] = cvt_f16x2(f1 - g2.y, f0 - g2.x);
                pl[mi][3] = cvt_f16x2(f3 - g3.y, f2 - g3.x);
            }
            #pragma unroll
            for (int d16 = 0; d16 < 4; d16++) {
                uint32_t vh4[4];
                ldsm4t(vh4, v_base + ksP * 2048 + vbo[d16]);
                #pragma unroll
                for (int mi = 0; mi < 2; mi++) {
                    mma16816(o[mi][2*d16],   ph[mi], vh4[0], vh4[1]);
                    mma16816(o[mi][2*d16],   pl[mi], vh4[0], vh4[1]);
                    mma16816(o[mi][2*d16+1], ph[mi], vh4[2], vh4[3]);
                    mma16816(o[mi][2*d16+1], pl[mi], vh4[2], vh4[3]);
                }
            }
        }
        if (cc + 2 < nch) issueKV(cc + 2);
    }

    #pragma unroll
    for (int mi = 0; mi < 2; mi++) {
        int rp0 = p0 + mi * 16 + (lane >> 2);
        int rp1 = rp0 + 8;
        int nm0 = maskp[b * S_ + 2 * rp0] | maskp[b * S_ + 2 * rp0 + 1];
        int nm1 = maskp[b * S_ + 2 * rp1] | maskp[b * S_ + 2 * rp1 + 1];
        float s0v = nm0 ? (1.0f / lsum[mi][0]) : 0.0f;
        float s1v = nm1 ? (1.0f / lsum[mi][1]) : 0.0f;
        float* dst0 = out + (size_t)(b * P_ + rp0) * D_ + h * 64 + (lane & 3) * 2;
        float* dst1 = out + (size_t)(b * P_ + rp1) * D_ + h * 64 + (lane & 3) * 2;
        #pragma unroll
        for (int d8 = 0; d8 < 8; d8++) {
            *(float2*)(dst0 + d8 * 8) = make_float2(o[mi][d8][0] * s0v, o[mi][d8][1] * s0v);
            *(float2*)(dst1 + d8 * 8) = make_float2(o[mi][d8][2] * s1v, o[mi][d8][3] * s1v);
        }
    }
}

// ---------------- launch ----------------
extern "C" void kernel_launch(void* const* d_in, const int* in_sizes, int n_in,
                              void* d_out, int out_size)
{
    const float* hidden = (const float*)d_in[0];
    const int*   mask   = (const int*)d_in[1];
    const float* W      = (const float*)d_in[2];
    const float* Wb     = (const float*)d_in[3];
    float* out = (float*)d_out;

    float* resid = out + RQ_OFF;
    float* nmout = out + NM_OFF;

    (void)cudaFuncSetAttribute(gemm_all, cudaFuncAttributeMaxDynamicSharedMemorySize, SMEM_REQ);

    scan_a<<<B_, 512>>>(mask, nmout);
    scan_b<<<1, 1>>>();
    split_hidden<<<B_ * P_, 192>>>(hidden, mask, resid);
    split_wT<<<dim3(N3_/32, D_/32), dim3(32, 8)>>>(W);
    gemm_all<<<768 + 12*256, 128, SMEM_REQ>>>(Wb, resid);
    attn_mma<<<dim3(2, H_, B_), 128>>>(mask, resid, out);
}